// round 9
// baseline (speedup 1.0000x reference)
#include <cuda_runtime.h>
#include <math.h>

// Problem constants
#define PN   4096
#define TT   128
#define AA   32
#define KEL  409          // int(4096 * 0.1)
#define INFF 1e30f

// ---------------- scratch (no allocations allowed) ----------------
__device__ float g_dists[PN];
__device__ int   g_eidx[KEL];
__device__ float g_edist[KEL];
__device__ float g_w[KEL];
__device__ float g_scalars[2];       // [0] = ssum, [1] = 1/(ssum+1e-9)
__device__ float g_p1[TT][4][AA];    // stats partials: sum(w*x)
__device__ float g_p2[TT][4][AA];    // stats partials: sum(w*x*x)

// =====================================================================
// Kernel A: DTW min-plus DP. TWO problems per warp, fully interleaved.
// Row recurrence new[j] = min(min(prev[j+1],prev[j]), new[j-1]) + c[j]
// solved per row as: s = prefix_sum(c); new[j] = s[j] + prefmin(m[k]-s_ex[k])
// Lane owns 4 consecutive columns. Row i+1's +scan is computed during row
// i's min-scan; the four SHFL chains (2 problems x 2 scans) interleave so
// their 26-cycle latencies overlap. Min-scans are unpredicated (idempotent).
// =====================================================================
struct DtwState {
    float v0, v1, v2, v3;     // prev-row DP values (D_prev[j+1])
    float s0, s1, s2, s3;     // current-row inclusive global prefix sums
    float base;               // current-row exclusive prefix (lane base)
    float4 cn;                // next-row costs
};

__global__ void __launch_bounds__(256) dtw_kernel(const float* __restrict__ obs) {
    const unsigned FULL = 0xffffffffu;
    int warpId = (blockIdx.x * blockDim.x + threadIdx.x) >> 5;
    int lane   = threadIdx.x & 31;
    if (warpId >= PN / 2) return;

    const float4* baseA = (const float4*)(obs + (size_t)(2 * warpId)     * TT * TT);
    const float4* baseB = (const float4*)(obs + (size_t)(2 * warpId + 1) * TT * TT);

    DtwState A, B;

    // ---------------- prologue ----------------
    // Row 0 result is exactly the inclusive prefix sum of row 0 costs.
    // Scan row0(A), row0(B), row1(A), row1(B) sums — all four interleaved.
    {
        float4 a0 = baseA[lane];
        float4 b0 = baseB[lane];
        float4 a1 = baseA[32 + lane];
        float4 b1 = baseB[32 + lane];

        float a0s0 = a0.x, a0s1 = a0s0 + a0.y, a0s2 = a0s1 + a0.z, a0s3 = a0s2 + a0.w;
        float b0s0 = b0.x, b0s1 = b0s0 + b0.y, b0s2 = b0s1 + b0.z, b0s3 = b0s2 + b0.w;
        float a1s0 = a1.x, a1s1 = a1s0 + a1.y, a1s2 = a1s1 + a1.z, a1s3 = a1s2 + a1.w;
        float b1s0 = b1.x, b1s1 = b1s0 + b1.y, b1s2 = b1s1 + b1.z, b1s3 = b1s2 + b1.w;

        float sa0 = a0s3, sb0 = b0s3, sa1 = a1s3, sb1 = b1s3;
        #pragma unroll
        for (int off = 1; off < 32; off <<= 1) {
            float t0 = __shfl_up_sync(FULL, sa0, off);
            float t1 = __shfl_up_sync(FULL, sb0, off);
            float t2 = __shfl_up_sync(FULL, sa1, off);
            float t3 = __shfl_up_sync(FULL, sb1, off);
            if (lane >= off) { sa0 += t0; sb0 += t1; sa1 += t2; sb1 += t3; }
        }
        float bA0 = sa0 - a0s3, bB0 = sb0 - b0s3;
        float bA1 = sa1 - a1s3, bB1 = sb1 - b1s3;

        // v = row0 DP result = global prefix sums of row 0
        A.v0 = a0s0 + bA0; A.v1 = a0s1 + bA0; A.v2 = a0s2 + bA0; A.v3 = a0s3 + bA0;
        B.v0 = b0s0 + bB0; B.v1 = b0s1 + bB0; B.v2 = b0s2 + bB0; B.v3 = b0s3 + bB0;
        // s/base for row 1
        A.s0 = a1s0 + bA1; A.s1 = a1s1 + bA1; A.s2 = a1s2 + bA1; A.s3 = a1s3 + bA1;
        B.s0 = b1s0 + bB1; B.s1 = b1s1 + bB1; B.s2 = b1s2 + bB1; B.s3 = b1s3 + bB1;
        A.base = bA1; B.base = bB1;

        A.cn = baseA[64 + lane];   // row 2 costs
        B.cn = baseB[64 + lane];
    }

    // ---------------- main loop: rows 1..127 ----------------
    #pragma unroll 2
    for (int i = 1; i < TT; i++) {
        int nl = (i + 2 < TT) ? (i + 2) : (TT - 1);
        float4 fA = baseA[nl * 32 + lane];
        float4 fB = baseB[nl * 32 + lane];

        // next-row local sums (independent of v chains)
        float Ans0 = A.cn.x, Ans1 = Ans0 + A.cn.y, Ans2 = Ans1 + A.cn.z, Ans3 = Ans2 + A.cn.w;
        float Bns0 = B.cn.x, Bns1 = Bns0 + B.cn.y, Bns2 = Bns1 + B.cn.z, Bns3 = Bns2 + B.cn.w;

        // current-row min-chain setup
        float upA = __shfl_up_sync(FULL, A.v3, 1);
        float upB = __shfl_up_sync(FULL, B.v3, 1);
        float shA = (lane == 0) ? INFF : upA;
        float shB = (lane == 0) ? INFF : upB;

        float Am0 = fminf(A.v0, shA), Am1 = fminf(A.v1, A.v0);
        float Am2 = fminf(A.v2, A.v1), Am3 = fminf(A.v3, A.v2);
        float Bm0 = fminf(B.v0, shB), Bm1 = fminf(B.v1, B.v0);
        float Bm2 = fminf(B.v2, B.v1), Bm3 = fminf(B.v3, B.v2);

        float At0 = Am0 - A.base, At1 = Am1 - A.s0, At2 = Am2 - A.s1, At3 = Am3 - A.s2;
        float Bt0 = Bm0 - B.base, Bt1 = Bm1 - B.s0, Bt2 = Bm2 - B.s1, Bt3 = Bm3 - B.s2;

        float Ap0 = At0, Ap1 = fminf(Ap0, At1), Ap2 = fminf(Ap1, At2), Ap3 = fminf(Ap2, At3);
        float Bp0 = Bt0, Bp1 = fminf(Bp0, Bt1), Bp2 = fminf(Bp1, Bt2), Bp3 = fminf(Bp2, Bt3);

        // interleaved warp scans: 2x +scan (next sums), 2x min-scan (current)
        float sumA = Ans3, sumB = Bns3, mnA = Ap3, mnB = Bp3;
        #pragma unroll
        for (int off = 1; off < 32; off <<= 1) {
            float ta = __shfl_up_sync(FULL, sumA, off);
            float tb = __shfl_up_sync(FULL, sumB, off);
            float ma = __shfl_up_sync(FULL, mnA, off);
            float mb = __shfl_up_sync(FULL, mnB, off);
            if (lane >= off) { sumA += ta; sumB += tb; }
            mnA = fminf(mnA, ma);      // unpredicated: OOB shfl returns own value
            mnB = fminf(mnB, mb);
        }

        float exA = __shfl_up_sync(FULL, mnA, 1);
        float exB = __shfl_up_sync(FULL, mnB, 1);
        if (lane == 0) { exA = INFF; exB = INFF; }

        float nbA = sumA - Ans3;
        float nbB = sumB - Bns3;

        A.v0 = A.s0 + fminf(Ap0, exA); A.v1 = A.s1 + fminf(Ap1, exA);
        A.v2 = A.s2 + fminf(Ap2, exA); A.v3 = A.s3 + fminf(Ap3, exA);
        B.v0 = B.s0 + fminf(Bp0, exB); B.v1 = B.s1 + fminf(Bp1, exB);
        B.v2 = B.s2 + fminf(Bp2, exB); B.v3 = B.s3 + fminf(Bp3, exB);

        A.base = nbA; A.s0 = Ans0 + nbA; A.s1 = Ans1 + nbA; A.s2 = Ans2 + nbA; A.s3 = Ans3 + nbA;
        B.base = nbB; B.s0 = Bns0 + nbB; B.s1 = Bns1 + nbB; B.s2 = Bns2 + nbB; B.s3 = Bns3 + nbB;
        A.cn = fA; B.cn = fB;
    }

    if (lane == 31) {
        g_dists[2 * warpId]     = A.v3;   // D[T][T]
        g_dists[2 * warpId + 1] = B.v3;
    }
}

// =====================================================================
// Kernel B: exact top-K selection via rank counting (permutation ranks).
// =====================================================================
__global__ void __launch_bounds__(256) rank_kernel() {
    __shared__ float sd[PN];
    for (int i = threadIdx.x; i < PN; i += blockDim.x) sd[i] = g_dists[i];
    __syncthreads();

    int warp = threadIdx.x >> 5;
    int lane = threadIdx.x & 31;

    #pragma unroll
    for (int e = 0; e < 4; e++) {
        int p = blockIdx.x * 32 + warp * 4 + e;
        float d = sd[p];
        int cnt = 0;
        #pragma unroll 4
        for (int j = lane; j < PN; j += 32) {
            float dj = sd[j];
            cnt += (dj < d) || (dj == d && j < p);
        }
        #pragma unroll
        for (int off = 16; off; off >>= 1)
            cnt += __shfl_down_sync(0xffffffffu, cnt, off);
        if (lane == 0 && cnt < KEL) {
            g_eidx[cnt]  = p;
            g_edist[cnt] = d;
        }
    }
}

// =====================================================================
// Kernel C: softmax-style elite scores. One block, 512 threads.
// =====================================================================
__global__ void __launch_bounds__(512) score_kernel() {
    __shared__ float sred[512];
    int tid = threadIdx.x;

    float d = (tid < KEL) ? g_edist[tid] : INFF;

    sred[tid] = d; __syncthreads();
    #pragma unroll
    for (int s = 256; s; s >>= 1) {
        if (tid < s) sred[tid] = fminf(sred[tid], sred[tid + s]);
        __syncthreads();
    }
    float mind = sred[0]; __syncthreads();

    float e = (tid < KEL) ? expf(0.5f * (mind - d)) : 0.0f;

    sred[tid] = e; __syncthreads();
    #pragma unroll
    for (int s = 256; s; s >>= 1) {
        if (tid < s) sred[tid] += sred[tid + s];
        __syncthreads();
    }
    float E = sred[0]; __syncthreads();

    float wk = e / E;
    if (tid < KEL) g_w[tid] = wk;

    sred[tid] = (tid < KEL) ? wk : 0.0f; __syncthreads();
    #pragma unroll
    for (int s = 256; s; s >>= 1) {
        if (tid < s) sred[tid] += sred[tid + s];
        __syncthreads();
    }
    if (tid == 0) {
        float ssum = sred[0];
        g_scalars[0] = ssum;
        g_scalars[1] = 1.0f / (ssum + 1e-9f);
    }
}

// =====================================================================
// Kernel D: elite-gathered weighted partial sums. Grid = T*4 (t x quarter),
// 256 threads. 4x the block-level parallelism of the previous version.
// =====================================================================
__global__ void __launch_bounds__(256) stats_partial_kernel(
    const float* __restrict__ noise,   // [T, P, A]
    const float* __restrict__ means,   // [T, 1, A]
    const float* __restrict__ stds)    // [T, 1, A]
{
    int t    = blockIdx.x >> 2;
    int q    = blockIdx.x & 3;
    int lane = threadIdx.x & 31;       // a index
    int warp = threadIdx.x >> 5;       // 0..7

    __shared__ float red1[8][32];
    __shared__ float red2[8][32];

    float mean_ta = means[t * AA + lane];
    float std_ta  = stds [t * AA + lane];
    const float* nbase = noise + (size_t)t * PN * AA;

    float S1 = 0.0f, S2 = 0.0f;
    // k = q*8 + warp + 32*it covers all k < KEL across the 4 quarters
    #pragma unroll 4
    for (int k = q * 8 + warp; k < KEL; k += 32) {
        float wk = g_w[k];
        int   p  = g_eidx[k];
        float x  = mean_ta + std_ta * __ldg(nbase + p * AA + lane); // coalesced 128B
        x = fminf(fmaxf(x, -1.0f), 1.0f);
        S1 += wk * x;
        S2 += wk * x * x;
    }
    red1[warp][lane] = S1;
    red2[warp][lane] = S2;
    __syncthreads();

    if (warp == 0) {
        float s1 = 0.0f, s2 = 0.0f;
        #pragma unroll
        for (int i = 0; i < 8; i++) { s1 += red1[i][lane]; s2 += red2[i][lane]; }
        g_p1[t][q][lane] = s1;
        g_p2[t][q][lane] = s2;
    }
}

// =====================================================================
// Kernel E: combine partials, final mean/std math. Grid = T, 32 threads.
// =====================================================================
__global__ void __launch_bounds__(32) stats_final_kernel(
    const float* __restrict__ means,
    const float* __restrict__ stds,
    float* __restrict__ out)           // [2, T, 1, A]
{
    int t    = blockIdx.x;
    int lane = threadIdx.x;

    float s1 = g_p1[t][0][lane] + g_p1[t][1][lane] + g_p1[t][2][lane] + g_p1[t][3][lane];
    float s2 = g_p2[t][0][lane] + g_p2[t][1][lane] + g_p2[t][2][lane] + g_p2[t][3][lane];

    float mean_ta = means[t * AA + lane];
    float W     = g_scalars[0];
    float recip = g_scalars[1];
    float mu  = s1 * recip;
    float var = fmaxf((s2 - 2.0f * mu * s1 + mu * mu * W) * recip, 0.0f);
    float sd  = fminf(fmaxf(sqrtf(var), 0.05f), 1.0f);

    out[t * AA + lane]           = 0.1f * mean_ta + 0.9f * mu;  // means_new
    out[TT * AA + t * AA + lane] = sd;                          // _std
}

// =====================================================================
extern "C" void kernel_launch(void* const* d_in, const int* in_sizes, int n_in,
                              void* d_out, int out_size) {
    const float* obs   = (const float*)d_in[0];  // [P, T, T]
    const float* means = (const float*)d_in[1];  // [T, 1, A]
    const float* stds  = (const float*)d_in[2];  // [T, 1, A]
    const float* noise = (const float*)d_in[3];  // [T, P, A]
    float* out = (float*)d_out;                  // [2, T, 1, A]

    dtw_kernel          <<<PN / 16, 256>>>(obs);   // 2048 warps, 2 problems each
    rank_kernel         <<<PN / 32, 256>>>();
    score_kernel        <<<1, 512>>>();
    stats_partial_kernel<<<TT * 4, 256>>>(noise, means, stds);
    stats_final_kernel  <<<TT, 32>>>(means, stds, out);
}